// round 9
// baseline (speedup 1.0000x reference)
#include <cuda_runtime.h>
#include <cuda_bf16.h>
#include <cstdint>

#define DIM 64
#define NUM_CODES 50000
#define NUM_Q 8192
#define NTILES 782            // ceil(50000/64)
#define QT 64
#define CT 64
#define STR 65                // smem row stride (conflict-free scalar access)

__device__ int g_is_bf16;     // 0 = buffers are f32, 1 = buffers are bf16

// ---- dtype probe: decide by low-16-bit sanity of the codes buffer ----
__global__ void nn_probe(const unsigned int* __restrict__ buf) {
    int lane = threadIdx.x;   // launched with 32 threads
    int sane = 0;
    for (int i = lane; i < 1024; i += 32) {
        unsigned int lo = buf[i] & 0xFFFFu;
        unsigned int ex = (lo >> 7) & 0xFFu;     // bf16 exponent field
        if (lo == 0u || (ex >= 96u && ex <= 160u)) sane++;
    }
    #pragma unroll
    for (int o = 16; o > 0; o >>= 1) sane += __shfl_xor_sync(0xFFFFFFFFu, sane, o);
    if (lane == 0) g_is_bf16 = (sane > 700) ? 1 : 0;
}

__device__ __forceinline__ float load_elem(const void* p, size_t idx, bool isbf) {
    if (isbf) return __bfloat162float(((const __nv_bfloat16*)p)[idx]);
    return ((const float*)p)[idx];
}

// ---- main kernel: direct squared distance + explicit argmin ----
// R9 single change: OUTPUT AS FLOAT32 (ids cast to float; -1.0f for no-code).
__global__ __launch_bounds__(256) void nn_direct(const void* __restrict__ x,
                                                 const void* __restrict__ codes,
                                                 float* __restrict__ out) {
    __shared__ float xs[QT * STR];
    __shared__ float cs[CT * STR];

    const int tid = threadIdx.x;
    const int tx = tid & 15;        // code direction: codes c = tx + 16*i
    const int ty = tid >> 4;        // query direction: queries q = ty + 16*j
    const int qbase = blockIdx.x * QT;
    const bool isbf = (g_is_bf16 != 0);

    // ---- load X tile [64 queries x 64 dims] ----
    #pragma unroll
    for (int i = 0; i < 16; i++) {
        int idx = tid + i * 256;
        int r = idx >> 6;
        int k = idx & 63;
        xs[r * STR + k] = load_elem(x, (size_t)(qbase + r) * DIM + k, isbf);
    }
    __syncthreads();

    float bd[4];
    int   bi[4];
    #pragma unroll
    for (int j = 0; j < 4; j++) { bd[j] = 3.4e38f; bi[j] = 0x7FFFFFFF; }

    for (int tile = 0; tile < NTILES; tile++) {
        const int cbase = tile * CT;

        __syncthreads();   // previous iteration's reads of cs complete

        // ---- load code tile [64 codes x 64 dims]; pad rows -> 1e15 ----
        #pragma unroll
        for (int i = 0; i < 16; i++) {
            int idx = tid + i * 256;
            int r = idx >> 6;
            int k = idx & 63;
            int gc = cbase + r;
            cs[r * STR + k] = (gc < NUM_CODES)
                ? load_elem(codes, (size_t)gc * DIM + k, isbf) : 1e15f;
        }
        __syncthreads();

        // ---- 4x4 register tile: direct sum of squared differences ----
        float acc[4][4];
        #pragma unroll
        for (int j = 0; j < 4; j++)
            #pragma unroll
            for (int i = 0; i < 4; i++) acc[j][i] = 0.f;

        #pragma unroll 4
        for (int k = 0; k < DIM; k++) {
            float xf[4], cf[4];
            #pragma unroll
            for (int j = 0; j < 4; j++) xf[j] = xs[(ty + 16 * j) * STR + k];
            #pragma unroll
            for (int i = 0; i < 4; i++) cf[i] = cs[(tx + 16 * i) * STR + k];
            #pragma unroll
            for (int j = 0; j < 4; j++) {
                #pragma unroll
                for (int i = 0; i < 4; i++) {
                    float t = xf[j] - cf[i];
                    acc[j][i] = fmaf(t, t, acc[j][i]);
                }
            }
        }

        // ---- running argmin (first-min tie break) ----
        #pragma unroll
        for (int j = 0; j < 4; j++) {
            #pragma unroll
            for (int i = 0; i < 4; i++) {
                int cidx = cbase + tx + 16 * i;
                float d = acc[j][i];
                if (d < bd[j] || (d == bd[j] && cidx < bi[j])) {
                    bd[j] = d;
                    bi[j] = cidx;
                }
            }
        }
    }

    // ---- reduce across the 16 lanes sharing each query ----
    #pragma unroll
    for (int j = 0; j < 4; j++) {
        #pragma unroll
        for (int o = 8; o > 0; o >>= 1) {
            float od = __shfl_xor_sync(0xFFFFFFFFu, bd[j], o);
            int   oi = __shfl_xor_sync(0xFFFFFFFFu, bi[j], o);
            if (od < bd[j] || (od == bd[j] && oi < bi[j])) {
                bd[j] = od;
                bi[j] = oi;
            }
        }
    }

    if (tx == 0) {
        #pragma unroll
        for (int j = 0; j < 4; j++) {
            int q = qbase + ty + 16 * j;
            out[q] = (bd[j] <= 100.0f) ? (float)bi[j] : -1.0f;
        }
    }
}

extern "C" void kernel_launch(void* const* d_in, const int* in_sizes, int n_in,
                              void* d_out, int out_size) {
    // Scan ALL inputs (no position/count assumptions):
    //   codes: 3200000 elements (12800000 bytes)
    //   x:      524288 elements ( 2097152 bytes)
    // Fallback: largest input = codes, next largest = x.
    const void* x = nullptr;
    const void* codes = nullptr;
    for (int i = 0; i < n_in; i++) {
        long long s = in_sizes[i];
        if (s == 3200000LL || s == 12800000LL) codes = d_in[i];
        else if (s == 524288LL || s == 2097152LL) x = d_in[i];
    }
    if (x == nullptr || codes == nullptr) {
        int imax = 0;
        for (int i = 1; i < n_in; i++) if (in_sizes[i] > in_sizes[imax]) imax = i;
        int iother = (imax == 0) ? 1 : 0;
        for (int i = 0; i < n_in; i++)
            if (i != imax && in_sizes[i] > in_sizes[iother]) iother = i;
        codes = d_in[imax];
        x = d_in[iother];
    }
    float* out = (float*)d_out;

    nn_probe<<<1, 32>>>((const unsigned int*)codes);
    nn_direct<<<NUM_Q / QT, 256>>>(x, codes, out);
}

// round 11
// speedup vs baseline: 1.8717x; 1.8717x over previous
#include <cuda_runtime.h>
#include <cuda_bf16.h>
#include <cstdint>

#define DIM 64
#define NUM_CODES 50000
#define NUM_Q 8192
#define QT 64                 // queries per tile
#define CT 96                 // codes per tile
#define NQT (NUM_Q / QT)      // 128 query tiles
#define NCT ((NUM_CODES + CT - 1) / CT)   // 521 code tiles
#define TOTAL_ITEMS (NQT * NCT)           // 66688
#define GRID 296              // 2 CTAs per SM on 148 SMs
#define XSTR 68               // xsT row stride (words): 68 mod 32 = 4 -> conflict-free
#define CSTR 100              // csT row stride (words): 100 mod 32 = 4 -> conflict-free

__device__ unsigned long long g_best[NUM_Q];

// ---------- helpers ----------
__device__ __forceinline__ unsigned long long pack2(float a, float b) {
    unsigned long long u;
    asm("mov.b64 %0, {%1,%2};" : "=l"(u) : "f"(a), "f"(b));
    return u;
}
__device__ __forceinline__ void unpack2(unsigned long long u, float &a, float &b) {
    asm("mov.b64 {%0,%1}, %2;" : "=f"(a), "=f"(b) : "l"(u));
}
__device__ __forceinline__ void ffma2(unsigned long long &acc, unsigned long long a, unsigned long long b) {
    asm("fma.rn.f32x2 %0, %1, %2, %0;" : "+l"(acc) : "l"(a), "l"(b));
}

__global__ void nn_init_best() {
    int i = blockIdx.x * blockDim.x + threadIdx.x;
    if (i < NUM_Q) g_best[i] = 0xFFFFFFFFFFFFFFFFull;
}

// ---------- main kernel ----------
// Persistent CTAs over a flat (qtile, ctile) item list.
// Thread map: tx = tid%16 (codes: 6 codes = 3 interleaved pairs), ty = tid/16 (4 queries).
// smem tiles are k-major (transposed). Code columns are pair-interleaved:
//   col = 2p + s  holds code  p + s*48   (p = 0..47, s = 0/1)
// so one aligned 8-byte LDS yields an FFMA2-ready pair of two codes.
__global__ __launch_bounds__(256, 2) void nn_main(const float* __restrict__ x,
                                                  const float* __restrict__ codes) {
    __shared__ float xsT[DIM * XSTR];   // [k][q]   64 x 64 (stride 68)
    __shared__ float csT[DIM * CSTR];   // [k][col] 64 x 96 (stride 100)
    __shared__ float x2s[QT];
    __shared__ float c2s[CT];

    const int tid = threadIdx.x;
    const int tx = tid & 15;
    const int ty = tid >> 4;

    // contiguous item range for this CTA
    const int per = (TOTAL_ITEMS + GRID - 1) / GRID;            // 226
    int i0 = blockIdx.x * per;
    int i1 = i0 + per; if (i1 > TOTAL_ITEMS) i1 = TOTAL_ITEMS;

    unsigned long long best[4];
    #pragma unroll
    for (int j = 0; j < 4; j++) best[j] = 0xFFFFFFFFFFFFFFFFull;

    int cur_qt = -1;

    for (int item = i0; item < i1; item++) {
        const int qt = item / NCT;
        const int ct = item - qt * NCT;
        const int cbase = ct * CT;

        __syncthreads();   // previous item's smem reads complete

        if (qt != cur_qt) {
            // flush accumulated bests for the previous q-tile
            if (cur_qt >= 0) {
                #pragma unroll
                for (int j = 0; j < 4; j++) {
                    #pragma unroll
                    for (int o = 8; o > 0; o >>= 1) {
                        unsigned long long v = __shfl_xor_sync(0xFFFFFFFFu, best[j], o);
                        if (v < best[j]) best[j] = v;
                    }
                }
                if (tx == 0) {
                    int qb = cur_qt * QT;
                    #pragma unroll
                    for (int j = 0; j < 4; j++)
                        atomicMin(&g_best[qb + ty * 4 + j], best[j]);
                }
                #pragma unroll
                for (int j = 0; j < 4; j++) best[j] = 0xFFFFFFFFFFFFFFFFull;
            }
            cur_qt = qt;
            // load x tile transposed: col-fastest so STS banks are conflict-free
            const int qb = qt * QT;
            #pragma unroll
            for (int i = 0; i < 4; i++) {
                int f = tid + i * 256;          // 0..1023
                int col = f & 63;               // query within tile
                int k4 = f >> 6;                // which float4 along k (0..15)
                float4 v = *reinterpret_cast<const float4*>(x + (size_t)(qb + col) * DIM + k4 * 4);
                xsT[(k4 * 4 + 0) * XSTR + col] = v.x;
                xsT[(k4 * 4 + 1) * XSTR + col] = v.y;
                xsT[(k4 * 4 + 2) * XSTR + col] = v.z;
                xsT[(k4 * 4 + 3) * XSTR + col] = v.w;
            }
        }

        // load code tile transposed + pair-interleaved, col-fastest
        #pragma unroll
        for (int i = 0; i < 6; i++) {
            int f = tid + i * 256;              // 0..1535
            int col = f % CT;                   // 0..95
            int k4 = f / CT;                    // 0..15
            int gid = cbase + (col >> 1) + (col & 1) * 48;
            float4 v;
            if (gid < NUM_CODES)
                v = *reinterpret_cast<const float4*>(codes + (size_t)gid * DIM + k4 * 4);
            else
                v = make_float4(1e15f, 1e15f, 1e15f, 1e15f);
            csT[(k4 * 4 + 0) * CSTR + col] = v.x;
            csT[(k4 * 4 + 1) * CSTR + col] = v.y;
            csT[(k4 * 4 + 2) * CSTR + col] = v.z;
            csT[(k4 * 4 + 3) * CSTR + col] = v.w;
        }
        __syncthreads();

        // norms (column reads are conflict-free: strides == 4 mod 32)
        if (tid < QT) {
            float s = 0.f;
            #pragma unroll 8
            for (int k = 0; k < DIM; k++) {
                float v = xsT[k * XSTR + tid];
                s = fmaf(v, v, s);
            }
            x2s[tid] = s;
        } else if (tid < QT + CT) {
            int col = tid - QT;
            float s = 0.f;
            #pragma unroll 8
            for (int k = 0; k < DIM; k++) {
                float v = csT[k * CSTR + col];
                s = fmaf(v, v, s);
            }
            c2s[col] = s;
        }
        __syncthreads();

        // ---- dot products: 4 queries x 3 code-pairs, FFMA2 over paired codes ----
        unsigned long long acc[4][3];
        #pragma unroll
        for (int j = 0; j < 4; j++)
            #pragma unroll
            for (int u = 0; u < 3; u++) acc[j][u] = 0ull;

        #pragma unroll 8
        for (int k = 0; k < DIM; k++) {
            float4 xf = *reinterpret_cast<const float4*>(&xsT[k * XSTR + ty * 4]);
            unsigned long long xd0 = pack2(xf.x, xf.x);
            unsigned long long xd1 = pack2(xf.y, xf.y);
            unsigned long long xd2 = pack2(xf.z, xf.z);
            unsigned long long xd3 = pack2(xf.w, xf.w);
            const float* crow = &csT[k * CSTR + tx * 6];
            unsigned long long cp0 = *reinterpret_cast<const unsigned long long*>(crow + 0);
            unsigned long long cp1 = *reinterpret_cast<const unsigned long long*>(crow + 2);
            unsigned long long cp2 = *reinterpret_cast<const unsigned long long*>(crow + 4);
            ffma2(acc[0][0], xd0, cp0); ffma2(acc[0][1], xd0, cp1); ffma2(acc[0][2], xd0, cp2);
            ffma2(acc[1][0], xd1, cp0); ffma2(acc[1][1], xd1, cp1); ffma2(acc[1][2], xd1, cp2);
            ffma2(acc[2][0], xd2, cp0); ffma2(acc[2][1], xd2, cp1); ffma2(acc[2][2], xd2, cp2);
            ffma2(acc[3][0], xd3, cp0); ffma2(acc[3][1], xd3, cp1); ffma2(acc[3][2], xd3, cp2);
        }
        // FFMA2 lanes accumulate (lo,hi) = (x_k*c_lo_k, x_k*c_hi_k) summed over all k
        // -> lo/hi are full dot products for the two interleaved codes of the pair.

        // ---- epilogue: distances + running argmin ----
        #pragma unroll
        for (int j = 0; j < 4; j++) {
            float xq = x2s[ty * 4 + j];
            #pragma unroll
            for (int u = 0; u < 3; u++) {
                float dlo, dhi;
                unpack2(acc[j][u], dlo, dhi);
                int col = tx * 6 + 2 * u;
                float Dlo = fmaxf(fmaf(-2.f, dlo, xq + c2s[col]), 0.f);
                float Dhi = fmaxf(fmaf(-2.f, dhi, xq + c2s[col + 1]), 0.f);
                unsigned idlo = (unsigned)(cbase + tx * 3 + u);
                unsigned idhi = idlo + 48u;
                unsigned long long vlo = ((unsigned long long)__float_as_uint(Dlo) << 32) | idlo;
                unsigned long long vhi = ((unsigned long long)__float_as_uint(Dhi) << 32) | idhi;
                if (vlo < best[j]) best[j] = vlo;
                if (vhi < best[j]) best[j] = vhi;
            }
        }
    }

    // final flush
    if (cur_qt >= 0) {
        #pragma unroll
        for (int j = 0; j < 4; j++) {
            #pragma unroll
            for (int o = 8; o > 0; o >>= 1) {
                unsigned long long v = __shfl_xor_sync(0xFFFFFFFFu, best[j], o);
                if (v < best[j]) best[j] = v;
            }
        }
        if (tx == 0) {
            int qb = cur_qt * QT;
            #pragma unroll
            for (int j = 0; j < 4; j++)
                atomicMin(&g_best[qb + ty * 4 + j], best[j]);
        }
    }
}

// ---------- finalize: threshold + FLOAT output (the R9 contract discovery) ----------
__global__ void nn_finalize(float* __restrict__ out) {
    int i = blockIdx.x * blockDim.x + threadIdx.x;
    if (i >= NUM_Q) return;
    unsigned long long v = g_best[i];
    float d = __uint_as_float((unsigned)(v >> 32));
    int idx = (int)(unsigned)(v & 0xFFFFFFFFu);
    out[i] = (d <= 100.0f) ? (float)idx : -1.0f;
}

extern "C" void kernel_launch(void* const* d_in, const int* in_sizes, int n_in,
                              void* d_out, int out_size) {
    // size-based binding (proven in R9): codes = 3200000 elems, x = 524288 elems
    const float* x = nullptr;
    const float* codes = nullptr;
    for (int i = 0; i < n_in; i++) {
        long long s = in_sizes[i];
        if (s == 3200000LL || s == 12800000LL) codes = (const float*)d_in[i];
        else if (s == 524288LL || s == 2097152LL) x = (const float*)d_in[i];
    }
    if (x == nullptr || codes == nullptr) {
        int imax = 0;
        for (int i = 1; i < n_in; i++) if (in_sizes[i] > in_sizes[imax]) imax = i;
        int iother = (imax == 0) ? 1 : 0;
        for (int i = 0; i < n_in; i++)
            if (i != imax && in_sizes[i] > in_sizes[iother]) iother = i;
        codes = (const float*)d_in[imax];
        x = (const float*)d_in[iother];
    }
    float* out = (float*)d_out;

    nn_init_best<<<(NUM_Q + 255) / 256, 256>>>();
    nn_main<<<GRID, 256>>>(x, codes);
    nn_finalize<<<(NUM_Q + 255) / 256, 256>>>(out);
}

// round 14
// speedup vs baseline: 3.0910x; 1.6514x over previous
#include <cuda_runtime.h>
#include <cuda_bf16.h>
#include <mma.h>
#include <cstdint>
using namespace nvcuda;

#define DIM 64
#define NUM_CODES 50000
#define NUM_Q 8192
#define QTILE 128
#define NTILE 64
#define NQT (NUM_Q / QTILE)            // 64
#define NCT 782                        // ceil(50000/64)
#define CODES_PAD (NCT * NTILE)        // 50048
#define KAUG 256                       // [hi|lo|hi|lo] x [hi|hi|lo|lo]
#define KW (KAUG / 2)                  // 128 u32 words per augmented row
#define TOTAL_ITEMS (NQT * NCT)        // 50048
#define GRID 296                       // 2 CTAs per SM x 148 SMs
#define LDA 264                        // smem A leading dim (elems), conflict-free
#define LDB 264
#define LDD 68

#define SZ_A (QTILE * LDA * 2)                 // 67584 B
#define SZ_U 34816                             // max(NTILE*LDB*2=33792, QTILE*LDD*4=34816)
#define OFF_U SZ_A
#define OFF_C2 (SZ_A + SZ_U)                   // 102400
#define SMEM_TOTAL (OFF_C2 + NTILE * 4)        // 102656 B

__device__ unsigned long long g_best[NUM_Q];
__device__ float g_x2[NUM_Q];
__device__ float g_c2[CODES_PAD];
__device__ uint32_t g_xa[(size_t)NUM_Q * KW];        // 4 MB
__device__ uint32_t g_ca[(size_t)CODES_PAD * KW];    // 25.6 MB

__device__ __forceinline__ uint32_t bfpack(float a, float b) {
    unsigned short ua = __bfloat16_as_ushort(__float2bfloat16(a));
    unsigned short ub = __bfloat16_as_ushort(__float2bfloat16(b));
    return (uint32_t)ua | ((uint32_t)ub << 16);
}
__device__ __forceinline__ float blo(float v) {
    return v - __bfloat162float(__float2bfloat16(v));
}

__global__ void nn_init_best() {
    int i = blockIdx.x * blockDim.x + threadIdx.x;
    if (i < NUM_Q) g_best[i] = 0xFFFFFFFFFFFFFFFFull;
}

// one warp per query row: build [hi|lo|hi|lo] augmented bf16 row + fp32 norm
__global__ void nn_prep_x(const float* __restrict__ x) {
    int w = (blockIdx.x * blockDim.x + threadIdx.x) >> 5;
    int lane = threadIdx.x & 31;
    if (w >= NUM_Q) return;
    float2 v = reinterpret_cast<const float2*>(x + (size_t)w * DIM)[lane];
    float s = v.x * v.x + v.y * v.y;
    #pragma unroll
    for (int o = 16; o > 0; o >>= 1) s += __shfl_xor_sync(0xFFFFFFFFu, s, o);
    uint32_t hi = bfpack(v.x, v.y);
    uint32_t lo = bfpack(blo(v.x), blo(v.y));
    uint32_t* row = g_xa + (size_t)w * KW;
    row[lane] = hi; row[32 + lane] = lo; row[64 + lane] = hi; row[96 + lane] = lo;
    if (lane == 0) g_x2[w] = s;
}

// one warp per code row: [hi|hi|lo|lo]; pad rows -> zeros, norm 1e30
__global__ void nn_prep_c(const float* __restrict__ codes) {
    int w = (blockIdx.x * blockDim.x + threadIdx.x) >> 5;
    int lane = threadIdx.x & 31;
    if (w >= CODES_PAD) return;
    uint32_t* row = g_ca + (size_t)w * KW;
    if (w >= NUM_CODES) {
        row[lane] = 0u; row[32 + lane] = 0u; row[64 + lane] = 0u; row[96 + lane] = 0u;
        if (lane == 0) g_c2[w] = 1e30f;
        return;
    }
    float2 v = reinterpret_cast<const float2*>(codes + (size_t)w * DIM)[lane];
    float s = v.x * v.x + v.y * v.y;
    #pragma unroll
    for (int o = 16; o > 0; o >>= 1) s += __shfl_xor_sync(0xFFFFFFFFu, s, o);
    uint32_t hi = bfpack(v.x, v.y);
    uint32_t lo = bfpack(blo(v.x), blo(v.y));
    row[lane] = hi; row[32 + lane] = hi; row[64 + lane] = lo; row[96 + lane] = lo;
    if (lane == 0) g_c2[w] = s;
}

__global__ __launch_bounds__(256, 2) void nn_gemm() {
    extern __shared__ unsigned char smem[];
    __nv_bfloat16* As = reinterpret_cast<__nv_bfloat16*>(smem);
    __nv_bfloat16* Bs = reinterpret_cast<__nv_bfloat16*>(smem + OFF_U);
    float*         Ds = reinterpret_cast<float*>(smem + OFF_U);     // union with Bs
    float*         c2s = reinterpret_cast<float*>(smem + OFF_C2);
    uint32_t* As32 = reinterpret_cast<uint32_t*>(As);
    uint32_t* Bs32 = reinterpret_cast<uint32_t*>(Bs);

    const int tid = threadIdx.x;
    const int wid = tid >> 5;
    const int warp_m = wid & 3;        // 4 warps along M (32 rows each)
    const int warp_n = wid >> 2;       // 2 warps along N (32 cols each)

    const int per = (TOTAL_ITEMS + GRID - 1) / GRID;   // 170
    int i0 = blockIdx.x * per;
    int i1 = i0 + per; if (i1 > TOTAL_ITEMS) i1 = TOTAL_ITEMS;

    unsigned long long best = 0xFFFFFFFFFFFFFFFFull;
    float xq = 0.f;
    int cur_qt = -1;

    for (int item = i0; item < i1; item++) {
        const int qt = item / NCT;
        const int ct = item - qt * NCT;
        const int cbase = ct * NTILE;

        __syncthreads();                      // prev epilogue done (D/union free)

        if (qt != cur_qt) {
            if (cur_qt >= 0) {                // flush bests for previous q-tile
                unsigned long long o = __shfl_xor_sync(0xFFFFFFFFu, best, 1);
                if (o < best) best = o;
                if ((tid & 1) == 0)
                    atomicMin(&g_best[cur_qt * QTILE + (tid >> 1)], best);
                best = 0xFFFFFFFFFFFFFFFFull;
            }
            cur_qt = qt;
            const int qbase = qt * QTILE;
            // load A tile (128 rows x 128 u32) via uint4, 16 per thread
            #pragma unroll
            for (int i = 0; i < 16; i++) {
                int idx = i * 256 + tid;           // 0..4095
                int r = idx >> 5;                  // row
                int wd = idx & 31;                 // uint4 within row
                uint4 v = reinterpret_cast<const uint4*>(g_xa + (size_t)(qbase + r) * KW)[wd];
                *reinterpret_cast<uint4*>(As32 + r * (LDA / 2) + wd * 4) = v;
            }
            xq = g_x2[qbase + (tid >> 1)];
        }

        // load B tile (64 rows x 128 u32) via uint4, 8 per thread; + c2s
        #pragma unroll
        for (int i = 0; i < 8; i++) {
            int idx = i * 256 + tid;               // 0..2047
            int r = idx >> 5;
            int wd = idx & 31;
            uint4 v = reinterpret_cast<const uint4*>(g_ca + (size_t)(cbase + r) * KW)[wd];
            *reinterpret_cast<uint4*>(Bs32 + r * (LDB / 2) + wd * 4) = v;
        }
        if (tid < NTILE) c2s[tid] = g_c2[cbase + tid];
        __syncthreads();

        // ---- WMMA: 2x2 m16n16k16 fragments per warp, 16 k-steps ----
        wmma::fragment<wmma::accumulator, 16, 16, 16, float> acc[2][2];
        #pragma unroll
        for (int i = 0; i < 2; i++)
            #pragma unroll
            for (int j = 0; j < 2; j++) wmma::fill_fragment(acc[i][j], 0.0f);

        #pragma unroll
        for (int k = 0; k < KAUG / 16; k++) {
            wmma::fragment<wmma::matrix_a, 16, 16, 16, __nv_bfloat16, wmma::row_major> af[2];
            wmma::fragment<wmma::matrix_b, 16, 16, 16, __nv_bfloat16, wmma::col_major> bf[2];
            #pragma unroll
            for (int i = 0; i < 2; i++)
                wmma::load_matrix_sync(af[i], As + (warp_m * 32 + i * 16) * LDA + k * 16, LDA);
            #pragma unroll
            for (int j = 0; j < 2; j++)
                wmma::load_matrix_sync(bf[j], Bs + (warp_n * 32 + j * 16) * LDB + k * 16, LDB);
            #pragma unroll
            for (int i = 0; i < 2; i++)
                #pragma unroll
                for (int j = 0; j < 2; j++)
                    wmma::mma_sync(acc[i][j], af[i], bf[j], acc[i][j]);
        }

        __syncthreads();                      // all warps done reading Bs
        #pragma unroll
        for (int i = 0; i < 2; i++)
            #pragma unroll
            for (int j = 0; j < 2; j++)
                wmma::store_matrix_sync(Ds + (warp_m * 32 + i * 16) * LDD + warp_n * 32 + j * 16,
                                        acc[i][j], LDD, wmma::mem_row_major);
        __syncthreads();

        // ---- epilogue: 2 threads per query, 32 codes each ----
        const int q = tid >> 1;
        const int ch = (tid & 1) * 32;
        #pragma unroll 8
        for (int i = 0; i < 32; i++) {
            int c = ch + i;
            float dot = Ds[q * LDD + c];
            float d = fmaxf(fmaf(-2.f, dot, xq + c2s[c]), 0.f);
            unsigned long long v =
                ((unsigned long long)__float_as_uint(d) << 32) | (unsigned)(cbase + c);
            if (v < best) best = v;
        }
    }

    if (cur_qt >= 0) {
        unsigned long long o = __shfl_xor_sync(0xFFFFFFFFu, best, 1);
        if (o < best) best = o;
        if ((tid & 1) == 0)
            atomicMin(&g_best[cur_qt * QTILE + (tid >> 1)], best);
    }
}

__global__ void nn_finalize(float* __restrict__ out) {
    int i = blockIdx.x * blockDim.x + threadIdx.x;
    if (i >= NUM_Q) return;
    unsigned long long v = g_best[i];
    float d = __uint_as_float((unsigned)(v >> 32));
    int idx = (int)(unsigned)(v & 0xFFFFFFFFu);
    out[i] = (d <= 100.0f) ? (float)idx : -1.0f;
}

extern "C" void kernel_launch(void* const* d_in, const int* in_sizes, int n_in,
                              void* d_out, int out_size) {
    // size-based binding (proven): codes = 3200000 elems, x = 524288 elems
    const float* x = nullptr;
    const float* codes = nullptr;
    for (int i = 0; i < n_in; i++) {
        long long s = in_sizes[i];
        if (s == 3200000LL || s == 12800000LL) codes = (const float*)d_in[i];
        else if (s == 524288LL || s == 2097152LL) x = (const float*)d_in[i];
    }
    if (x == nullptr || codes == nullptr) {
        int imax = 0;
        for (int i = 1; i < n_in; i++) if (in_sizes[i] > in_sizes[imax]) imax = i;
        int iother = (imax == 0) ? 1 : 0;
        for (int i = 0; i < n_in; i++)
            if (i != imax && in_sizes[i] > in_sizes[iother]) iother = i;
        codes = (const float*)d_in[imax];
        x = (const float*)d_in[iother];
    }
    float* out = (float*)d_out;

    cudaFuncSetAttribute(nn_gemm, cudaFuncAttributeMaxDynamicSharedMemorySize, SMEM_TOTAL);

    nn_init_best<<<(NUM_Q + 255) / 256, 256>>>();
    nn_prep_x<<<(NUM_Q * 32 + 255) / 256, 256>>>(x);
    nn_prep_c<<<(CODES_PAD * 32 + 255) / 256, 256>>>(codes);
    nn_gemm<<<GRID, 256, SMEM_TOTAL>>>();
    nn_finalize<<<(NUM_Q + 255) / 256, 256>>>(out);
}

// round 15
// speedup vs baseline: 5.6169x; 1.8172x over previous
#include <cuda_runtime.h>
#include <cuda_bf16.h>
#include <cstdint>

#define DIM 64
#define NUM_CODES 50000
#define NUM_Q 8192
#define QTILE 128
#define NTILE 64
#define NQT 64
#define NCT 782
#define CODES_PAD (NCT * NTILE)        // 50048
#define TOTAL_ITEMS (NQT * NCT)        // 50048
#define GRID 296
#define K2 128                          // stored K per row: [hi(64) | lo(64)] bf16
#define KW (K2 / 2)                     // 64 u32 words per row
#define ROWB 272                        // smem row bytes (136 elems): 16B-aligned, 4-bank shift

#define OFF_A   0
#define SZ_A    (QTILE * ROWB)          // 34816
#define OFF_B0  SZ_A
#define SZ_B    (NTILE * ROWB)          // 17408
#define OFF_B1  (OFF_B0 + SZ_B)
#define OFF_C0  (OFF_B1 + SZ_B)         // 69632
#define OFF_C1  (OFF_C0 + 256)
#define SMEM_TOTAL (OFF_C1 + 256)       // 70144

__device__ unsigned long long g_best[NUM_Q];
__device__ float g_x2[NUM_Q];
__device__ float g_c2[CODES_PAD];
__device__ uint32_t g_xa[(size_t)NUM_Q * KW];       // 2 MB  [hi|lo]
__device__ uint32_t g_ca[(size_t)CODES_PAD * KW];   // 12.8 MB [hi|lo]

__device__ __forceinline__ uint32_t smem_to_u32(const void* p) {
    uint32_t a;
    asm("{ .reg .u64 t; cvta.to.shared.u64 t, %1; cvt.u32.u64 %0, t; }" : "=r"(a) : "l"(p));
    return a;
}
__device__ __forceinline__ uint32_t bfpack(float a, float b) {
    unsigned short ua = __bfloat16_as_ushort(__float2bfloat16(a));
    unsigned short ub = __bfloat16_as_ushort(__float2bfloat16(b));
    return (uint32_t)ua | ((uint32_t)ub << 16);
}
__device__ __forceinline__ float blo(float v) {
    return v - __bfloat162float(__float2bfloat16(v));
}

#define LDSM4(r, addr) \
    asm volatile("ldmatrix.sync.aligned.m8n8.x4.shared.b16 {%0,%1,%2,%3}, [%4];" \
                 : "=r"((r)[0]), "=r"((r)[1]), "=r"((r)[2]), "=r"((r)[3]) : "r"(addr))
#define MMA(d, a, b0_, b1_) \
    asm volatile("mma.sync.aligned.m16n8k16.row.col.f32.bf16.bf16.f32 " \
                 "{%0,%1,%2,%3}, {%4,%5,%6,%7}, {%8,%9}, {%0,%1,%2,%3};" \
                 : "+f"((d)[0]), "+f"((d)[1]), "+f"((d)[2]), "+f"((d)[3]) \
                 : "r"((a)[0]), "r"((a)[1]), "r"((a)[2]), "r"((a)[3]), "r"(b0_), "r"(b1_))
#define CP_COMMIT() asm volatile("cp.async.commit_group;" ::: "memory")
#define CP_WAIT1()  asm volatile("cp.async.wait_group 1;" ::: "memory")

__global__ void nn_init_best() {
    int i = blockIdx.x * blockDim.x + threadIdx.x;
    if (i < NUM_Q) g_best[i] = 0xFFFFFFFFFFFFFFFFull;
}

__global__ void nn_prep_x(const float* __restrict__ x) {
    int w = (blockIdx.x * blockDim.x + threadIdx.x) >> 5;
    int lane = threadIdx.x & 31;
    if (w >= NUM_Q) return;
    float2 v = reinterpret_cast<const float2*>(x + (size_t)w * DIM)[lane];
    float s = v.x * v.x + v.y * v.y;
    #pragma unroll
    for (int o = 16; o > 0; o >>= 1) s += __shfl_xor_sync(0xFFFFFFFFu, s, o);
    uint32_t* row = g_xa + (size_t)w * KW;
    row[lane] = bfpack(v.x, v.y);
    row[32 + lane] = bfpack(blo(v.x), blo(v.y));
    if (lane == 0) g_x2[w] = s;
}

__global__ void nn_prep_c(const float* __restrict__ codes) {
    int w = (blockIdx.x * blockDim.x + threadIdx.x) >> 5;
    int lane = threadIdx.x & 31;
    if (w >= CODES_PAD) return;
    uint32_t* row = g_ca + (size_t)w * KW;
    if (w >= NUM_CODES) {
        row[lane] = 0u; row[32 + lane] = 0u;
        if (lane == 0) g_c2[w] = 1e30f;
        return;
    }
    float2 v = reinterpret_cast<const float2*>(codes + (size_t)w * DIM)[lane];
    float s = v.x * v.x + v.y * v.y;
    #pragma unroll
    for (int o = 16; o > 0; o >>= 1) s += __shfl_xor_sync(0xFFFFFFFFu, s, o);
    row[lane] = bfpack(v.x, v.y);
    row[32 + lane] = bfpack(blo(v.x), blo(v.y));
    if (lane == 0) g_c2[w] = s;
}

__device__ __forceinline__ void prefetch_b(uint32_t sbase, int offB, int offC, int cbase, int tid) {
    #pragma unroll
    for (int i = 0; i < 4; i++) {
        int idx = i * 256 + tid;              // 0..1023
        int r = idx >> 4, ch = idx & 15;
        uint32_t dst = sbase + offB + r * ROWB + ch * 16;
        const char* src = reinterpret_cast<const char*>(g_ca + (size_t)(cbase + r) * KW) + ch * 16;
        asm volatile("cp.async.cg.shared.global [%0], [%1], 16;" :: "r"(dst), "l"(src));
    }
    if (tid < 16) {
        uint32_t dst = sbase + offC + tid * 16;
        const char* src = reinterpret_cast<const char*>(g_c2 + cbase) + tid * 16;
        asm volatile("cp.async.cg.shared.global [%0], [%1], 16;" :: "r"(dst), "l"(src));
    }
}

__device__ __forceinline__ void flush_best(float* bd, int* bi, int qt, int warp_m, int lane) {
    #pragma unroll
    for (int e = 0; e < 4; e++) {
        #pragma unroll
        for (int o = 1; o <= 2; o <<= 1) {
            float od = __shfl_xor_sync(0xFFFFFFFFu, bd[e], o);
            int   oi = __shfl_xor_sync(0xFFFFFFFFu, bi[e], o);
            if (od < bd[e] || (od == bd[e] && oi < bi[e])) { bd[e] = od; bi[e] = oi; }
        }
        if ((lane & 3) == 0) {
            int q = qt * QTILE + warp_m * 32 + (e >> 1) * 16 + (e & 1) * 8 + (lane >> 2);
            unsigned long long v =
                ((unsigned long long)__float_as_uint(bd[e]) << 32) | (unsigned)bi[e];
            atomicMin(&g_best[q], v);
        }
    }
}

__global__ __launch_bounds__(256, 2) void nn_gemm() {
    extern __shared__ unsigned char smem[];
    const uint32_t sbase = smem_to_u32(smem);
    uint32_t* As32 = reinterpret_cast<uint32_t*>(smem + OFF_A);

    const int tid = threadIdx.x;
    const int lane = tid & 31;
    const int wid = tid >> 5;
    const int warp_m = wid & 3;          // 4 warps along M (32 rows)
    const int warp_n = wid >> 2;         // 2 warps along N (32 cols)

    // ldmatrix per-thread address components
    const int rA  = lane & 15;                       // A: lanes 0-15 rows, 16-31 rows (k+8)
    const int kA8 = (lane >> 4) * 8;
    const int rB  = ((lane >> 4) * 8) + (lane & 7);  // B: n-row within 16-chunk
    const int kB8 = ((lane >> 3) & 1) * 8;

    const uint32_t aBase = sbase + OFF_A;
    const uint32_t aOff0 = (uint32_t)((warp_m * 32 + rA) * ROWB + kA8 * 2);
    const uint32_t bOff0 = (uint32_t)((warp_n * 32 + rB) * ROWB + kB8 * 2);

    const int per = (TOTAL_ITEMS + GRID - 1) / GRID;
    int i0 = blockIdx.x * per;
    int i1 = i0 + per; if (i1 > TOTAL_ITEMS) i1 = TOTAL_ITEMS;
    if (i0 >= i1) return;

    float bd[4]; int bi[4];
    #pragma unroll
    for (int e = 0; e < 4; e++) { bd[e] = 3.4e38f; bi[e] = 0x7FFFFFFF; }
    float xq[4] = {0.f, 0.f, 0.f, 0.f};
    int cur_qt = -1;
    int buf = 0;

    prefetch_b(sbase, OFF_B0, OFF_C0, (i0 % NCT) * NTILE, tid);
    CP_COMMIT();

    for (int item = i0; item < i1; item++) {
        const int qt = item / NCT;
        const int ct = item - qt * NCT;
        const int cbase = ct * NTILE;

        if (qt != cur_qt) {
            __syncthreads();                    // all warps done reading old A
            if (cur_qt >= 0) {
                flush_best(bd, bi, cur_qt, warp_m, lane);
                #pragma unroll
                for (int e = 0; e < 4; e++) { bd[e] = 3.4e38f; bi[e] = 0x7FFFFFFF; }
            }
            cur_qt = qt;
            const int qbase = qt * QTILE;
            #pragma unroll
            for (int i = 0; i < 8; i++) {       // A tile: 2048 uint4
                int idx = i * 256 + tid;
                int r = idx >> 4, w = idx & 15;
                uint4 v = reinterpret_cast<const uint4*>(g_xa + (size_t)(qbase + r) * KW)[w];
                *reinterpret_cast<uint4*>(reinterpret_cast<char*>(As32) + r * ROWB + w * 16) = v;
            }
            #pragma unroll
            for (int e = 0; e < 4; e++)
                xq[e] = g_x2[qbase + warp_m * 32 + (e >> 1) * 16 + (e & 1) * 8 + (lane >> 2)];
        }

        __syncthreads();                        // buf^1 fully consumed (2 tiles ago) + A visible
        if (item + 1 < i1) {
            int nxt = item + 1;
            int nct = nxt - (nxt / NCT) * NCT;
            prefetch_b(sbase, buf ? OFF_B0 : OFF_B1, buf ? OFF_C0 : OFF_C1, nct * NTILE, tid);
        }
        CP_COMMIT();
        CP_WAIT1();                             // current tile's B landed
        __syncthreads();

        const uint32_t bBase = sbase + (buf ? OFF_B1 : OFF_B0);
        const float* c2s = reinterpret_cast<const float*>(smem + (buf ? OFF_C1 : OFF_C0));

        float c2r[8];
        #pragma unroll
        for (int nf = 0; nf < 4; nf++) {
            c2r[nf * 2 + 0] = c2s[warp_n * 32 + nf * 8 + 2 * (lane & 3) + 0];
            c2r[nf * 2 + 1] = c2s[warp_n * 32 + nf * 8 + 2 * (lane & 3) + 1];
        }

        float acc[2][4][4];
        #pragma unroll
        for (int mf = 0; mf < 2; mf++)
            #pragma unroll
            for (int nf = 0; nf < 4; nf++)
                #pragma unroll
                for (int r = 0; r < 4; r++) acc[mf][nf][r] = 0.f;

        #pragma unroll
        for (int ah = 0; ah < 2; ah++) {
            uint32_t a[4][2][4];                // cached A frags for this half
            #pragma unroll
            for (int k4 = 0; k4 < 4; k4++)
                #pragma unroll
                for (int mf = 0; mf < 2; mf++)
                    LDSM4(a[k4][mf], aBase + aOff0 + mf * (16 * ROWB) + ah * 128 + k4 * 32);
            #pragma unroll
            for (int bh = 0; bh < 2; bh++) {
                #pragma unroll
                for (int k4 = 0; k4 < 4; k4++) {
                    uint32_t b0[4], b1[4];
                    LDSM4(b0, bBase + bOff0 + bh * 128 + k4 * 32);
                    LDSM4(b1, bBase + bOff0 + 16 * ROWB + bh * 128 + k4 * 32);
                    #pragma unroll
                    for (int mf = 0; mf < 2; mf++) {
                        MMA(acc[mf][0], a[k4][mf], b0[0], b0[1]);
                        MMA(acc[mf][1], a[k4][mf], b0[2], b0[3]);
                        MMA(acc[mf][2], a[k4][mf], b1[0], b1[1]);
                        MMA(acc[mf][3], a[k4][mf], b1[2], b1[3]);
                    }
                }
            }
        }

        // fused register epilogue: ascending (nf, b) -> ascending idx; strict < keeps first
        #pragma unroll
        for (int nf = 0; nf < 4; nf++)
            #pragma unroll
            for (int b = 0; b < 2; b++) {
                int col = warp_n * 32 + nf * 8 + 2 * (lane & 3) + b;
                int idx = cbase + col;
                float cc = c2r[nf * 2 + b];
                #pragma unroll
                for (int mf = 0; mf < 2; mf++)
                    #pragma unroll
                    for (int rh = 0; rh < 2; rh++) {
                        int e = mf * 2 + rh;
                        float D = fmaxf(fmaf(-2.f, acc[mf][nf][rh * 2 + b], xq[e] + cc), 0.f);
                        if (D < bd[e]) { bd[e] = D; bi[e] = idx; }
                    }
            }
        buf ^= 1;
    }

    flush_best(bd, bi, cur_qt, warp_m, lane);
}

__global__ void nn_finalize(float* __restrict__ out) {
    int i = blockIdx.x * blockDim.x + threadIdx.x;
    if (i >= NUM_Q) return;
    unsigned long long v = g_best[i];
    float d = __uint_as_float((unsigned)(v >> 32));
    int idx = (int)(unsigned)(v & 0xFFFFFFFFu);
    out[i] = (d <= 100.0f) ? (float)idx : -1.0f;
}

extern "C" void kernel_launch(void* const* d_in, const int* in_sizes, int n_in,
                              void* d_out, int out_size) {
    const float* x = nullptr;
    const float* codes = nullptr;
    for (int i = 0; i < n_in; i++) {
        long long s = in_sizes[i];
        if (s == 3200000LL || s == 12800000LL) codes = (const float*)d_in[i];
        else if (s == 524288LL || s == 2097152LL) x = (const float*)d_in[i];
    }
    if (x == nullptr || codes == nullptr) {
        int imax = 0;
        for (int i = 1; i < n_in; i++) if (in_sizes[i] > in_sizes[imax]) imax = i;
        int iother = (imax == 0) ? 1 : 0;
        for (int i = 0; i < n_in; i++)
            if (i != imax && in_sizes[i] > in_sizes[iother]) iother = i;
        codes = (const float*)d_in[imax];
        x = (const float*)d_in[iother];
    }
    float* out = (float*)d_out;

    cudaFuncSetAttribute(nn_gemm, cudaFuncAttributeMaxDynamicSharedMemorySize, SMEM_TOTAL);

    nn_init_best<<<(NUM_Q + 255) / 256, 256>>>();
    nn_prep_x<<<NUM_Q * 32 / 256, 256>>>(x);
    nn_prep_c<<<CODES_PAD * 32 / 256, 256>>>(codes);
    nn_gemm<<<GRID, 256, SMEM_TOTAL>>>();
    nn_finalize<<<(NUM_Q + 255) / 256, 256>>>(out);
}